// round 12
// baseline (speedup 1.0000x reference)
#include <cuda_runtime.h>

// LIF spike neuron scan — float2, U=32 load double-buffer, smem-staged 64-deep
// store bursts (DRAM pattern per warp: R32,R32,W64 instead of R32,W32,R32,W32).
// Each thread owns 2 adjacent chains. Block = 1 warp; smem spike staging is
// thread-private (each thread writes/reads only its own lane column), so no
// __syncthreads is needed.
// x: [B,S,N] fp32, m0: [B,N] fp32.
// out (fp32): spikes [B,S,N] flattened, then m_final [B,N].
// B=32, S=1024, N=2048.

#define B_DIM 32
#define S_DIM 1024
#define N_DIM 2048
#define DECAY 0.8f
#define THRESH 0.5f
#define U 32            // timesteps per load stage
#define BLK 32          // threads per block (1 warp)

#define N2 (N_DIM / 2)  // float2 columns per row = 1024

__global__ __launch_bounds__(BLK) void lif_scan_kernel(
    const float* __restrict__ x,
    const float* __restrict__ m0,
    float* __restrict__ out)
{
    __shared__ float2 sm[2 * U][BLK];   // 64 x 32 x 8B = 16 KB spike staging

    const int lane = threadIdx.x;
    const int p = blockIdx.x * BLK + lane;          // float2-chain index
    const int b  = p >> 10;                         // / N2
    const int n2 = p & (N2 - 1);                    // % N2

    const float2* __restrict__ xp =
        (const float2*)(x + (size_t)b * S_DIM * N_DIM) + n2;
    float2* __restrict__ sp =
        (float2*)(out + (size_t)b * S_DIM * N_DIM) + n2;
    const float2* __restrict__ m0p = (const float2*)m0 + p;
    float2* __restrict__ mfin =
        (float2*)(out + (size_t)B_DIM * S_DIM * N_DIM) + p;

    float2 mv = *m0p;
    float mx = mv.x, my = mv.y;

    float2 a[U], bb[U];

    // Compute U steps from src[] into the smem staging tile at row offset rbase.
    #define LIF_STAGE_SMEM(src, rbase)                                         \
        do {                                                                   \
            _Pragma("unroll")                                                  \
            for (int k = 0; k < U; k++) {                                      \
                mx = DECAY * mx + (src)[k].x;                                  \
                my = DECAY * my + (src)[k].y;                                  \
                const bool fx = (mx > THRESH);                                 \
                const bool fy = (my > THRESH);                                 \
                sm[(rbase) + k][lane] =                                        \
                    make_float2(fx ? 1.0f : 0.0f, fy ? 1.0f : 0.0f);           \
                mx = fx ? 0.0f : mx;                                           \
                my = fy ? 0.0f : my;                                           \
            }                                                                  \
        } while (0)

    // Prologue: load stage 0
    #pragma unroll
    for (int k = 0; k < U; k++)
        a[k] = __ldcs(xp + (size_t)k * N2);

    #pragma unroll 1
    for (int t = 0; t < S_DIM; t += 2 * U) {
        // Prefetch stage t+U while computing stage t
        #pragma unroll
        for (int k = 0; k < U; k++)
            bb[k] = __ldcs(xp + (size_t)(t + U + k) * N2);

        LIF_STAGE_SMEM(a, 0);

        // Prefetch stage t+2U (guarded) while computing stage t+U
        if (t + 2 * U < S_DIM) {
            #pragma unroll
            for (int k = 0; k < U; k++)
                a[k] = __ldcs(xp + (size_t)(t + 2 * U + k) * N2);
        }

        LIF_STAGE_SMEM(bb, U);

        // Flush: one 64-deep STG.64 burst for timesteps [t, t+64)
        #pragma unroll
        for (int k = 0; k < 2 * U; k++)
            __stcs(sp + (size_t)(t + k) * N2, sm[k][lane]);
    }

    *mfin = make_float2(mx, my);
}

extern "C" void kernel_launch(void* const* d_in, const int* in_sizes, int n_in,
                              void* d_out, int out_size)
{
    const float* x  = (const float*)d_in[0];
    const float* m0 = (const float*)d_in[1];
    float* out = (float*)d_out;

    const int total2 = (B_DIM * N_DIM) / 2;   // 32768 float2 chains
    const int blocks = total2 / BLK;          // 1024 blocks of 32 threads
    lif_scan_kernel<<<blocks, BLK>>>(x, m0, out);
}

// round 13
// speedup vs baseline: 1.2030x; 1.2030x over previous
#include <cuda_runtime.h>

// LIF spike neuron scan — float2, 16-deep ping-pong load buffer, 64-deep
// register spike batch stored as one contiguous burst.
// Per-warp DRAM pattern per 64 steps: R16,R16,R16,R16 (compute between,
// no intervening writes) then W64  -> 2 R/W transitions instead of 4.
// Each thread owns 2 adjacent chains. x: [B,S,N] fp32, m0: [B,N] fp32.
// out (fp32): spikes [B,S,N] flattened, then m_final [B,N].
// B=32, S=1024, N=2048.

#define B_DIM 32
#define S_DIM 1024
#define N_DIM 2048
#define DECAY 0.8f
#define THRESH 0.5f
#define UL 16           // load-buffer depth (ping-pong)
#define SB 64           // spike-batch / store-burst depth
#define BLK 32          // threads per block (1 warp)

#define N2 (N_DIM / 2)  // float2 columns per row = 1024

__global__ __launch_bounds__(BLK) void lif_scan_kernel(
    const float* __restrict__ x,
    const float* __restrict__ m0,
    float* __restrict__ out)
{
    const int p = blockIdx.x * BLK + threadIdx.x;   // float2-chain index
    const int b  = p >> 10;                         // / N2
    const int n2 = p & (N2 - 1);                    // % N2

    const float2* __restrict__ xp =
        (const float2*)(x + (size_t)b * S_DIM * N_DIM) + n2;
    float2* __restrict__ sp =
        (float2*)(out + (size_t)b * S_DIM * N_DIM) + n2;
    const float2* __restrict__ m0p = (const float2*)m0 + p;
    float2* __restrict__ mfin =
        (float2*)(out + (size_t)B_DIM * S_DIM * N_DIM) + p;

    float2 mv = *m0p;
    float mx = mv.x, my = mv.y;

    float2 buf0[UL], buf1[UL];
    float2 s[SB];

    #define PREFETCH(dst, tstart)                                              \
        do {                                                                   \
            _Pragma("unroll")                                                  \
            for (int k = 0; k < UL; k++)                                       \
                (dst)[k] = __ldcs(xp + (size_t)((tstart) + k) * N2);           \
        } while (0)

    #define COMPUTE16(src, soff)                                               \
        do {                                                                   \
            _Pragma("unroll")                                                  \
            for (int k = 0; k < UL; k++) {                                     \
                mx = DECAY * mx + (src)[k].x;                                  \
                my = DECAY * my + (src)[k].y;                                  \
                const bool fx = (mx > THRESH);                                 \
                const bool fy = (my > THRESH);                                 \
                s[(soff) + k] =                                                \
                    make_float2(fx ? 1.0f : 0.0f, fy ? 1.0f : 0.0f);           \
                mx = fx ? 0.0f : mx;                                           \
                my = fy ? 0.0f : my;                                           \
            }                                                                  \
        } while (0)

    // Prologue: load steps [0,16)
    PREFETCH(buf0, 0);

    #pragma unroll 1
    for (int t = 0; t < S_DIM; t += SB) {
        PREFETCH(buf1, t + 16);
        COMPUTE16(buf0, 0);

        PREFETCH(buf0, t + 32);
        COMPUTE16(buf1, 16);

        PREFETCH(buf1, t + 48);
        COMPUTE16(buf0, 32);

        if (t + SB < S_DIM)
            PREFETCH(buf0, t + 64);
        COMPUTE16(buf1, 48);

        // One contiguous 64-deep store burst for timesteps [t, t+64)
        #pragma unroll
        for (int k = 0; k < SB; k++)
            __stcs(sp + (size_t)(t + k) * N2, s[k]);
    }

    *mfin = make_float2(mx, my);
}

extern "C" void kernel_launch(void* const* d_in, const int* in_sizes, int n_in,
                              void* d_out, int out_size)
{
    const float* x  = (const float*)d_in[0];
    const float* m0 = (const float*)d_in[1];
    float* out = (float*)d_out;

    const int total2 = (B_DIM * N_DIM) / 2;   // 32768 float2 chains
    const int blocks = total2 / BLK;          // 1024 blocks of 32 threads
    lif_scan_kernel<<<blocks, BLK>>>(x, m0, out);
}

// round 14
// speedup vs baseline: 1.2136x; 1.0087x over previous
#include <cuda_runtime.h>

// LIF spike neuron scan — float2, U=32 load double-buffer + full-stage store
// bursts. Stores use DEFAULT cache policy (not .cs): dirty lines accumulate in
// L2 and write back in batched eviction bursts, reducing R/W turnaround at the
// DRAM controller. Loads stay .cs (streaming, don't fight dirty lines).
// Each thread owns 2 adjacent chains. x: [B,S,N] fp32, m0: [B,N] fp32.
// out (fp32): spikes [B,S,N] flattened, then m_final [B,N].
// B=32, S=1024, N=2048.

#define B_DIM 32
#define S_DIM 1024
#define N_DIM 2048
#define DECAY 0.8f
#define THRESH 0.5f
#define U 32            // timesteps per load stage
#define HB 32           // store-burst length (full stage)
#define BLK 32          // threads per block (1 warp)

#define N2 (N_DIM / 2)  // float2 columns per row = 1024

__global__ __launch_bounds__(BLK) void lif_scan_kernel(
    const float* __restrict__ x,
    const float* __restrict__ m0,
    float* __restrict__ out)
{
    const int p = blockIdx.x * BLK + threadIdx.x;   // float2-chain index, 0..32767
    const int b  = p >> 10;                         // / N2
    const int n2 = p & (N2 - 1);                    // % N2

    const float2* __restrict__ xp =
        (const float2*)(x + (size_t)b * S_DIM * N_DIM) + n2;
    float2* __restrict__ sp =
        (float2*)(out + (size_t)b * S_DIM * N_DIM) + n2;
    const float2* __restrict__ m0p = (const float2*)m0 + p;
    float2* __restrict__ mfin =
        (float2*)(out + (size_t)B_DIM * S_DIM * N_DIM) + p;

    float2 mv = *m0p;
    float mx = mv.x, my = mv.y;

    float2 a[U], bb[U];
    float2 s[HB];   // spike batch: computed first, stored as one long burst

    // Compute HB steps from src[0..HB) into s[], then burst-store HB STG.64s.
    #define LIF_STAGE(src, tbase)                                              \
        do {                                                                   \
            _Pragma("unroll")                                                  \
            for (int k = 0; k < HB; k++) {                                     \
                mx = DECAY * mx + (src)[k].x;                                  \
                my = DECAY * my + (src)[k].y;                                  \
                const bool fx = (mx > THRESH);                                 \
                const bool fy = (my > THRESH);                                 \
                s[k] = make_float2(fx ? 1.0f : 0.0f, fy ? 1.0f : 0.0f);        \
                mx = fx ? 0.0f : mx;                                           \
                my = fy ? 0.0f : my;                                           \
            }                                                                  \
            _Pragma("unroll")                                                  \
            for (int k = 0; k < HB; k++)                                       \
                sp[(size_t)((tbase) + k) * N2] = s[k];  /* default policy */   \
        } while (0)

    // Prologue: load stage 0
    #pragma unroll
    for (int k = 0; k < U; k++)
        a[k] = __ldcs(xp + (size_t)k * N2);

    #pragma unroll 1
    for (int t = 0; t < S_DIM; t += 2 * U) {
        // Prefetch stage t+U while computing stage t
        #pragma unroll
        for (int k = 0; k < U; k++)
            bb[k] = __ldcs(xp + (size_t)(t + U + k) * N2);

        LIF_STAGE(a, t);

        // Prefetch stage t+2U (guarded) while computing stage t+U
        if (t + 2 * U < S_DIM) {
            #pragma unroll
            for (int k = 0; k < U; k++)
                a[k] = __ldcs(xp + (size_t)(t + 2 * U + k) * N2);
        }

        LIF_STAGE(bb, t + U);
    }

    *mfin = make_float2(mx, my);
}

extern "C" void kernel_launch(void* const* d_in, const int* in_sizes, int n_in,
                              void* d_out, int out_size)
{
    const float* x  = (const float*)d_in[0];
    const float* m0 = (const float*)d_in[1];
    float* out = (float*)d_out;

    const int total2 = (B_DIM * N_DIM) / 2;   // 32768 float2 chains
    const int blocks = total2 / BLK;          // 1024 blocks of 32 threads
    lif_scan_kernel<<<blocks, BLK>>>(x, m0, out);
}

// round 15
// speedup vs baseline: 1.2361x; 1.0186x over previous
#include <cuda_runtime.h>

// LIF spike neuron scan — FINAL: float2, U=32 load double-buffer + 32-deep
// register store bursts, .cs on both streams (measured optimum over 14 rounds:
// kernel 77.1us, 6.30 TB/s = ~98% of the mixed R/W stream ceiling on GB300).
// Each thread owns 2 adjacent chains. x: [B,S,N] fp32, m0: [B,N] fp32.
// out (fp32): spikes [B,S,N] flattened, then m_final [B,N].
// B=32, S=1024, N=2048.

#define B_DIM 32
#define S_DIM 1024
#define N_DIM 2048
#define DECAY 0.8f
#define THRESH 0.5f
#define U 32            // timesteps per load stage
#define HB 32           // store-burst length (full stage)
#define BLK 32          // threads per block (1 warp)

#define N2 (N_DIM / 2)  // float2 columns per row = 1024

__global__ __launch_bounds__(BLK) void lif_scan_kernel(
    const float* __restrict__ x,
    const float* __restrict__ m0,
    float* __restrict__ out)
{
    const int p = blockIdx.x * BLK + threadIdx.x;   // float2-chain index, 0..32767
    const int b  = p >> 10;                         // / N2
    const int n2 = p & (N2 - 1);                    // % N2

    const float2* __restrict__ xp =
        (const float2*)(x + (size_t)b * S_DIM * N_DIM) + n2;
    float2* __restrict__ sp =
        (float2*)(out + (size_t)b * S_DIM * N_DIM) + n2;
    const float2* __restrict__ m0p = (const float2*)m0 + p;
    float2* __restrict__ mfin =
        (float2*)(out + (size_t)B_DIM * S_DIM * N_DIM) + p;

    float2 mv = *m0p;
    float mx = mv.x, my = mv.y;

    float2 a[U], bb[U];
    float2 s[HB];   // spike batch: computed first, stored as one long burst

    // Compute HB steps from src[0..HB) into s[], then burst-store HB STG.64s.
    #define LIF_STAGE(src, tbase)                                              \
        do {                                                                   \
            _Pragma("unroll")                                                  \
            for (int k = 0; k < HB; k++) {                                     \
                mx = DECAY * mx + (src)[k].x;                                  \
                my = DECAY * my + (src)[k].y;                                  \
                const bool fx = (mx > THRESH);                                 \
                const bool fy = (my > THRESH);                                 \
                s[k] = make_float2(fx ? 1.0f : 0.0f, fy ? 1.0f : 0.0f);        \
                mx = fx ? 0.0f : mx;                                           \
                my = fy ? 0.0f : my;                                           \
            }                                                                  \
            _Pragma("unroll")                                                  \
            for (int k = 0; k < HB; k++)                                       \
                __stcs(sp + (size_t)((tbase) + k) * N2, s[k]);                 \
        } while (0)

    // Prologue: load stage 0
    #pragma unroll
    for (int k = 0; k < U; k++)
        a[k] = __ldcs(xp + (size_t)k * N2);

    #pragma unroll 1
    for (int t = 0; t < S_DIM; t += 2 * U) {
        // Prefetch stage t+U while computing stage t
        #pragma unroll
        for (int k = 0; k < U; k++)
            bb[k] = __ldcs(xp + (size_t)(t + U + k) * N2);

        LIF_STAGE(a, t);

        // Prefetch stage t+2U (guarded) while computing stage t+U
        if (t + 2 * U < S_DIM) {
            #pragma unroll
            for (int k = 0; k < U; k++)
                a[k] = __ldcs(xp + (size_t)(t + 2 * U + k) * N2);
        }

        LIF_STAGE(bb, t + U);
    }

    *mfin = make_float2(mx, my);
}

extern "C" void kernel_launch(void* const* d_in, const int* in_sizes, int n_in,
                              void* d_out, int out_size)
{
    const float* x  = (const float*)d_in[0];
    const float* m0 = (const float*)d_in[1];
    float* out = (float*)d_out;

    const int total2 = (B_DIM * N_DIM) / 2;   // 32768 float2 chains
    const int blocks = total2 / BLK;          // 1024 blocks of 32 threads
    lif_scan_kernel<<<blocks, BLK>>>(x, m0, out);
}

// round 16
// speedup vs baseline: 1.2407x; 1.0037x over previous
#include <cuda_runtime.h>

// LIF spike neuron scan — CONVERGED CONFIG (= R10, best bench 84.5us):
// float2 per thread, U=32 .cs load double-buffer, HB=16 register store bursts.
// 15 rounds established: latency/MLP fully hidden (cp.async 112KB/SM no gain),
// f2@1024x32 optimal width/thread trade, ~6.2-6.3 TB/s is the 50/50 R/W
// interleaved stream wall on GB300; this config sits at it.
// x: [B,S,N] fp32, m0: [B,N] fp32.
// out (fp32): spikes [B,S,N] flattened, then m_final [B,N].
// B=32, S=1024, N=2048.

#define B_DIM 32
#define S_DIM 1024
#define N_DIM 2048
#define DECAY 0.8f
#define THRESH 0.5f
#define U 32            // timesteps per load stage
#define HB 16           // store-burst length (half stage)
#define BLK 32          // threads per block (1 warp)

#define N2 (N_DIM / 2)  // float2 columns per row = 1024

__global__ __launch_bounds__(BLK) void lif_scan_kernel(
    const float* __restrict__ x,
    const float* __restrict__ m0,
    float* __restrict__ out)
{
    const int p = blockIdx.x * BLK + threadIdx.x;   // float2-chain index, 0..32767
    const int b  = p >> 10;                         // / N2
    const int n2 = p & (N2 - 1);                    // % N2

    const float2* __restrict__ xp =
        (const float2*)(x + (size_t)b * S_DIM * N_DIM) + n2;
    float2* __restrict__ sp =
        (float2*)(out + (size_t)b * S_DIM * N_DIM) + n2;
    const float2* __restrict__ m0p = (const float2*)m0 + p;
    float2* __restrict__ mfin =
        (float2*)(out + (size_t)B_DIM * S_DIM * N_DIM) + p;

    float2 mv = *m0p;
    float mx = mv.x, my = mv.y;

    float2 a[U], bb[U];
    float2 s[HB];   // spike batch: computed first, stored as one burst

    // Compute HB steps from src[off..off+HB) into s[], then burst-store.
    #define LIF_HALF(src, off, tbase)                                          \
        do {                                                                   \
            _Pragma("unroll")                                                  \
            for (int k = 0; k < HB; k++) {                                     \
                mx = DECAY * mx + (src)[(off) + k].x;                          \
                my = DECAY * my + (src)[(off) + k].y;                          \
                const bool fx = (mx > THRESH);                                 \
                const bool fy = (my > THRESH);                                 \
                s[k] = make_float2(fx ? 1.0f : 0.0f, fy ? 1.0f : 0.0f);        \
                mx = fx ? 0.0f : mx;                                           \
                my = fy ? 0.0f : my;                                           \
            }                                                                  \
            _Pragma("unroll")                                                  \
            for (int k = 0; k < HB; k++)                                       \
                __stcs(sp + (size_t)((tbase) + k) * N2, s[k]);                 \
        } while (0)

    // Prologue: load stage 0
    #pragma unroll
    for (int k = 0; k < U; k++)
        a[k] = __ldcs(xp + (size_t)k * N2);

    #pragma unroll 1
    for (int t = 0; t < S_DIM; t += 2 * U) {
        // Prefetch stage t+U while computing stage t
        #pragma unroll
        for (int k = 0; k < U; k++)
            bb[k] = __ldcs(xp + (size_t)(t + U + k) * N2);

        LIF_HALF(a, 0,  t);
        LIF_HALF(a, HB, t + HB);

        // Prefetch stage t+2U (guarded) while computing stage t+U
        if (t + 2 * U < S_DIM) {
            #pragma unroll
            for (int k = 0; k < U; k++)
                a[k] = __ldcs(xp + (size_t)(t + 2 * U + k) * N2);
        }

        LIF_HALF(bb, 0,  t + U);
        LIF_HALF(bb, HB, t + U + HB);
    }

    *mfin = make_float2(mx, my);
}

extern "C" void kernel_launch(void* const* d_in, const int* in_sizes, int n_in,
                              void* d_out, int out_size)
{
    const float* x  = (const float*)d_in[0];
    const float* m0 = (const float*)d_in[1];
    float* out = (float*)d_out;

    const int total2 = (B_DIM * N_DIM) / 2;   // 32768 float2 chains
    const int blocks = total2 / BLK;          // 1024 blocks of 32 threads
    lif_scan_kernel<<<blocks, BLK>>>(x, m0, out);
}